// round 9
// baseline (speedup 1.0000x reference)
#include <cuda_runtime.h>

// MacUnit: out[b, 2*ic+k] = attention[2*ic+k] * f3(data[b, ic])
// f3 = 3 iterations of x += step(x)/3 (tanh-indexed piecewise-linear trig).
//
// R9: (value, delta) float2 table on [-4,4], h=1/2048, 128KB in shared,
// 1 CTA/SM. R8 showed latency-bound (DRAM 35%, L1 54%, issue 20%): widen
// per-thread MLP to 4 front-batched LDG.128 per loop iteration + streaming
// cache hints (read-once data, write-once out). |x|>=4 -> exact MUFU path.

#define NUM_POINTS 17
#define TAB_INTERVALS 16384              // h = 1/2048 over [-4,4]
#define TAB_SCALE     2048.0f
#define TAB_H         (1.0f / 2048.0f)
#define TAB_BYTES     (TAB_INTERVALS * 8)   // 131072 B of float2

__device__ float2 g_tab[TAB_INTERVALS];

// Exact f3 for one value (rare path + table build).
__device__ __forceinline__ float f3_exact(float x, float c2l, float b2l,
                                          const float* __restrict__ angles,
                                          const float* __restrict__ velocity)
{
    #pragma unroll
    for (int s = 0; s < 3; s++) {
        float e;
        asm("ex2.approx.f32 %0, %1;" : "=f"(e) : "f"(fmaf(x, c2l, b2l)));
        float r;
        asm("rcp.approx.f32 %0, %1;" : "=f"(r) : "f"(e + 1.0f));
        float u = fmaf(r, -17.0f, 17.5f);   // index + 8, in (0.5, 17.5)
        int   si = (int)u;                  // trunc == floor (u > 0)
        float pos = u - (float)si;
        int bgn = si - 8;
        int end = bgn + 1;                  // end < 17 always
        int bw = bgn < 0 ? bgn + NUM_POINTS : bgn;   // torch negative wrap
        int ew = end < 0 ? end + NUM_POINTS : end;
        float vb = __ldg(&velocity[bw]) * (1.0f / 3.0f);
        float ve = __ldg(&velocity[ew]) * (1.0f / 3.0f);
        float ab = __ldg(&angles[bw]);
        float ae = __ldg(&angles[ew]);
        float velo3 = fmaf(pos, ve - vb, vb);
        float ang   = fmaf(pos, ae - ab, ab);
        float sn, cs;
        __sincosf(ang, &sn, &cs);
        x = fmaf(x, fmaf(velo3, sn, 1.0f), velo3 * cs);
    }
    return x;
}

// ---------------------------------------------------------------------------
// Kernel 1: build (value, delta) pair table.
// ---------------------------------------------------------------------------
__global__ __launch_bounds__(256)
void build_table_kernel(const float* __restrict__ angles,
                        const float* __restrict__ velocity,
                        const float* __restrict__ coeff,
                        const float* __restrict__ bias)
{
    const float c2l = __ldg(coeff) * 2.8853900817779268f;   // 2*log2(e)*c
    const float b2l = __ldg(bias)  * 2.8853900817779268f;
    const int i = blockIdx.x * 256 + threadIdx.x;
    if (i < TAB_INTERVALS) {
        float x0 = fmaf((float)i,       TAB_H, -4.0f);
        float x1 = fmaf((float)(i + 1), TAB_H, -4.0f);
        float v0 = f3_exact(x0, c2l, b2l, angles, velocity);
        float v1 = f3_exact(x1, c2l, b2l, angles, velocity);
        g_tab[i] = make_float2(v0, v1 - v0);
    }
}

// ---------------------------------------------------------------------------
// Kernel 2: persistent map. 128KB table in shared, 1 CTA/SM, 4-way ILP.
// ---------------------------------------------------------------------------
#define MAP_THREADS 1024
#define MAP_BLOCKS  304
#define TOTAL_G     ((32768 * 512) / 4)   // 4,194,304 float4 groups
#define ILP 4

extern __shared__ float2 s_tab[];

__global__ __launch_bounds__(MAP_THREADS)
void macunit_map_kernel(const float4* __restrict__ data,
                        const float4* __restrict__ att,
                        const float* __restrict__ angles,
                        const float* __restrict__ velocity,
                        const float* __restrict__ coeff,
                        const float* __restrict__ bias,
                        float4* __restrict__ out)
{
    // Stage pair table into shared memory.
    {
        const float2* gt = g_tab;
        for (int i = threadIdx.x; i < TAB_INTERVALS; i += MAP_THREADS)
            s_tab[i] = __ldg(&gt[i]);
    }
    __syncthreads();

    const float c2l = __ldg(coeff) * 2.8853900817779268f;
    const float b2l = __ldg(bias)  * 2.8853900817779268f;

    const int stride = MAP_BLOCKS * MAP_THREADS;
    int g0 = blockIdx.x * MAP_THREADS + threadIdx.x;

    while (g0 < TOTAL_G) {
        int    gs[ILP];
        float4 d[ILP];
        bool   ok[ILP];

        // Front-batch ILP independent LDG.128 (max outstanding loads).
        #pragma unroll
        for (int k = 0; k < ILP; k++) {
            gs[k] = g0 + k * stride;
            ok[k] = gs[k] < TOTAL_G;
            d[k]  = ok[k] ? __ldcs(&data[gs[k]]) : make_float4(0.f, 0.f, 0.f, 0.f);
        }

        #pragma unroll
        for (int k = 0; k < ILP; k++) {
            if (!ok[k]) break;
            const int g = gs[k];
            float xin[4] = {d[k].x, d[k].y, d[k].z, d[k].w};
            float y[4];

            #pragma unroll
            for (int j = 0; j < 4; j++) {
                float x = xin[j];
                if (fabsf(x) < 4.0f) {
                    float t = fmaf(x, TAB_SCALE, 4.0f * TAB_SCALE);  // (x+4)/h
                    int   i = (int)t;                                 // 0..16383
                    float fr = t - (float)i;
                    float2 vd = s_tab[i];                             // one LDS.64
                    y[j] = fmaf(fr, vd.y, vd.x);
                } else {
                    y[j] = f3_exact(x, c2l, b2l, angles, velocity);   // rare
                }
            }

            const int brow = g >> 7;             // 128 float4-groups/input row
            const int c4   = g & 127;

            const float4 a0 = __ldg(&att[2 * c4]);
            const float4 a1 = __ldg(&att[2 * c4 + 1]);

            float4 o0, o1;
            o0.x = a0.x * y[0];  o0.y = a0.y * y[0];
            o0.z = a0.z * y[1];  o0.w = a0.w * y[1];
            o1.x = a1.x * y[2];  o1.y = a1.y * y[2];
            o1.z = a1.z * y[3];  o1.w = a1.w * y[3];

            const int ob = brow * 256 + 2 * c4;  // 256 float4/output row
            __stcs(&out[ob],     o0);            // streaming: write-once
            __stcs(&out[ob + 1], o1);
        }

        g0 += ILP * stride;
    }
}

extern "C" void kernel_launch(void* const* d_in, const int* in_sizes, int n_in,
                              void* d_out, int out_size)
{
    const float4* data     = (const float4*)d_in[0];  // [32768, 512] f32
    const float*  angles   = (const float*) d_in[1];  // [17]
    const float*  velocity = (const float*) d_in[2];  // [17]
    const float4* att      = (const float4*)d_in[3];  // [1024] f32
    const float*  coeff    = (const float*) d_in[4];  // [1]
    const float*  bias     = (const float*) d_in[5];  // [1]
    float4* out = (float4*)d_out;

    static bool attr_set = false;
    if (!attr_set) {
        cudaFuncSetAttribute(macunit_map_kernel,
                             cudaFuncAttributeMaxDynamicSharedMemorySize,
                             TAB_BYTES);
        attr_set = true;
    }

    build_table_kernel<<<(TAB_INTERVALS + 255) / 256, 256>>>(angles, velocity, coeff, bias);

    macunit_map_kernel<<<MAP_BLOCKS, MAP_THREADS, TAB_BYTES>>>(
        data, att, angles, velocity, coeff, bias, out);
}

// round 11
// speedup vs baseline: 1.0583x; 1.0583x over previous
#include <cuda_runtime.h>

// MacUnit: out[b, 2*ic+k] = attention[2*ic+k] * f3(data[b, ic])
// f3 = 3 iterations of x += step(x)/3 (tanh-indexed piecewise-linear trig).
//
// R10: (value, delta) float2 table on [-4,4], h=1/1024 (8192 intervals, 64KB)
// in shared memory, 2 CTAs x 1024 thr per SM = full occupancy while leaving
// ~100KB L1D for global traffic (R6's 2-CTA failure used 192KB smem / 36KB
// L1D). Error model calibrated R5->R8: rel_err ~ h^1.5 => ~4.0e-4 here.
// |x|>=4 (6e-5 of N(0,1)) -> exact MUFU path.

#define NUM_POINTS 17
#define TAB_INTERVALS 8192               // h = 1/1024 over [-4,4]
#define TAB_SCALE     1024.0f
#define TAB_H         (1.0f / 1024.0f)
#define TAB_BYTES     (TAB_INTERVALS * 8)   // 65536 B of float2

__device__ float2 g_tab[TAB_INTERVALS];

// Exact f3 for one value (rare path + table build).
__device__ __forceinline__ float f3_exact(float x, float c2l, float b2l,
                                          const float* __restrict__ angles,
                                          const float* __restrict__ velocity)
{
    #pragma unroll
    for (int s = 0; s < 3; s++) {
        float e;
        asm("ex2.approx.f32 %0, %1;" : "=f"(e) : "f"(fmaf(x, c2l, b2l)));
        float r;
        asm("rcp.approx.f32 %0, %1;" : "=f"(r) : "f"(e + 1.0f));
        float u = fmaf(r, -17.0f, 17.5f);   // index + 8, in (0.5, 17.5)
        int   si = (int)u;                  // trunc == floor (u > 0)
        float pos = u - (float)si;
        int bgn = si - 8;
        int end = bgn + 1;                  // end < 17 always
        int bw = bgn < 0 ? bgn + NUM_POINTS : bgn;   // torch negative wrap
        int ew = end < 0 ? end + NUM_POINTS : end;
        float vb = __ldg(&velocity[bw]) * (1.0f / 3.0f);
        float ve = __ldg(&velocity[ew]) * (1.0f / 3.0f);
        float ab = __ldg(&angles[bw]);
        float ae = __ldg(&angles[ew]);
        float velo3 = fmaf(pos, ve - vb, vb);
        float ang   = fmaf(pos, ae - ab, ab);
        float sn, cs;
        __sincosf(ang, &sn, &cs);
        x = fmaf(x, fmaf(velo3, sn, 1.0f), velo3 * cs);
    }
    return x;
}

// ---------------------------------------------------------------------------
// Kernel 1: build (value, delta) pair table.
// ---------------------------------------------------------------------------
__global__ __launch_bounds__(256)
void build_table_kernel(const float* __restrict__ angles,
                        const float* __restrict__ velocity,
                        const float* __restrict__ coeff,
                        const float* __restrict__ bias)
{
    const float c2l = __ldg(coeff) * 2.8853900817779268f;   // 2*log2(e)*c
    const float b2l = __ldg(bias)  * 2.8853900817779268f;
    const int i = blockIdx.x * 256 + threadIdx.x;
    if (i < TAB_INTERVALS) {
        float x0 = fmaf((float)i,       TAB_H, -4.0f);
        float x1 = fmaf((float)(i + 1), TAB_H, -4.0f);
        float v0 = f3_exact(x0, c2l, b2l, angles, velocity);
        float v1 = f3_exact(x1, c2l, b2l, angles, velocity);
        g_tab[i] = make_float2(v0, v1 - v0);
    }
}

// ---------------------------------------------------------------------------
// Kernel 2: persistent map. 64KB table in shared, 2 CTAs/SM, 2-group ILP.
// ---------------------------------------------------------------------------
#define MAP_THREADS 1024
#define MAP_BLOCKS  304                   // 2 CTAs resident per SM x 152 SMs
#define TOTAL_G     ((32768 * 512) / 4)   // 4,194,304 float4 groups

extern __shared__ float2 s_tab[];

__device__ __forceinline__ void process_group(
    int g, const float4 d,
    const float4* __restrict__ att, float4* __restrict__ out,
    float c2l, float b2l,
    const float* __restrict__ angles, const float* __restrict__ velocity)
{
    float xin[4] = {d.x, d.y, d.z, d.w};
    float y[4];

    #pragma unroll
    for (int j = 0; j < 4; j++) {
        float x = xin[j];
        if (fabsf(x) < 4.0f) {
            float t = fmaf(x, TAB_SCALE, 4.0f * TAB_SCALE);   // (x+4)/h
            int   i = (int)t;                                  // 0..8191
            float fr = t - (float)i;
            float2 vd = s_tab[i];                              // one LDS.64
            y[j] = fmaf(fr, vd.y, vd.x);
        } else {
            y[j] = f3_exact(x, c2l, b2l, angles, velocity);    // ~6e-5 of samples
        }
    }

    const int brow = g >> 7;                 // 128 float4-groups/input row
    const int c4   = g & 127;

    const float4 a0 = __ldg(&att[2 * c4]);
    const float4 a1 = __ldg(&att[2 * c4 + 1]);

    float4 o0, o1;
    o0.x = a0.x * y[0];  o0.y = a0.y * y[0];
    o0.z = a0.z * y[1];  o0.w = a0.w * y[1];
    o1.x = a1.x * y[2];  o1.y = a1.y * y[2];
    o1.z = a1.z * y[3];  o1.w = a1.w * y[3];

    const int ob = brow * 256 + 2 * c4;      // 256 float4/output row
    out[ob]     = o0;
    out[ob + 1] = o1;
}

__global__ __launch_bounds__(MAP_THREADS)
void macunit_map_kernel(const float4* __restrict__ data,
                        const float4* __restrict__ att,
                        const float* __restrict__ angles,
                        const float* __restrict__ velocity,
                        const float* __restrict__ coeff,
                        const float* __restrict__ bias,
                        float4* __restrict__ out)
{
    // Stage pair table into shared memory.
    {
        const float2* gt = g_tab;
        for (int i = threadIdx.x; i < TAB_INTERVALS; i += MAP_THREADS)
            s_tab[i] = __ldg(&gt[i]);
    }
    __syncthreads();

    const float c2l = __ldg(coeff) * 2.8853900817779268f;
    const float b2l = __ldg(bias)  * 2.8853900817779268f;

    const int stride = MAP_BLOCKS * MAP_THREADS;
    int g = blockIdx.x * MAP_THREADS + threadIdx.x;

    while (g < TOTAL_G) {
        const int g2 = g + stride;
        // Issue both input loads up front (2x LDG.128 in flight).
        float4 d1 = data[g];
        float4 d2 = (g2 < TOTAL_G) ? data[g2] : make_float4(0.f, 0.f, 0.f, 0.f);

        process_group(g, d1, att, out, c2l, b2l, angles, velocity);
        if (g2 < TOTAL_G)
            process_group(g2, d2, att, out, c2l, b2l, angles, velocity);

        g += 2 * stride;
    }
}

extern "C" void kernel_launch(void* const* d_in, const int* in_sizes, int n_in,
                              void* d_out, int out_size)
{
    const float4* data     = (const float4*)d_in[0];  // [32768, 512] f32
    const float*  angles   = (const float*) d_in[1];  // [17]
    const float*  velocity = (const float*) d_in[2];  // [17]
    const float4* att      = (const float4*)d_in[3];  // [1024] f32
    const float*  coeff    = (const float*) d_in[4];  // [1]
    const float*  bias     = (const float*) d_in[5];  // [1]
    float4* out = (float4*)d_out;

    static bool attr_set = false;
    if (!attr_set) {
        cudaFuncSetAttribute(macunit_map_kernel,
                             cudaFuncAttributeMaxDynamicSharedMemorySize,
                             TAB_BYTES);
        attr_set = true;
    }

    build_table_kernel<<<(TAB_INTERVALS + 255) / 256, 256>>>(angles, velocity, coeff, bias);

    macunit_map_kernel<<<MAP_BLOCKS, MAP_THREADS, TAB_BYTES>>>(
        data, att, angles, velocity, coeff, bias, out);
}

// round 12
// speedup vs baseline: 1.1479x; 1.0846x over previous
#include <cuda_runtime.h>

// MacUnit: out[b, 2*ic+k] = attention[2*ic+k] * f3(data[b, ic])
// f3 = 3 iterations of x += step(x)/3 (tanh-indexed piecewise-linear trig).
//
// R12: output-driven mapping. Output float4 index o (channels 4c..4c+3 of row
// b = o>>8) needs exactly input float2 index o (channels 2c,2c+1): 1 LDG.64 +
// 2 table lookups + 1 fully-coalesced STG.128 per thread. The attention
// float4 index (o & 255) is loop-invariant (stride % 256 == 0) -> registers.
// Table: (value,delta) float2, [-4,4], h=1/1024, 64KB smem, 2 CTAs/SM.

#define NUM_POINTS 17
#define TAB_INTERVALS 8192               // h = 1/1024 over [-4,4]
#define TAB_SCALE     1024.0f
#define TAB_H         (1.0f / 1024.0f)
#define TAB_BYTES     (TAB_INTERVALS * 8)   // 65536 B of float2

__device__ float2 g_tab[TAB_INTERVALS];

// Exact f3 for one value (rare path + table build).
__device__ __forceinline__ float f3_exact(float x, float c2l, float b2l,
                                          const float* __restrict__ angles,
                                          const float* __restrict__ velocity)
{
    #pragma unroll
    for (int s = 0; s < 3; s++) {
        float e;
        asm("ex2.approx.f32 %0, %1;" : "=f"(e) : "f"(fmaf(x, c2l, b2l)));
        float r;
        asm("rcp.approx.f32 %0, %1;" : "=f"(r) : "f"(e + 1.0f));
        float u = fmaf(r, -17.0f, 17.5f);   // index + 8, in (0.5, 17.5)
        int   si = (int)u;                  // trunc == floor (u > 0)
        float pos = u - (float)si;
        int bgn = si - 8;
        int end = bgn + 1;                  // end < 17 always
        int bw = bgn < 0 ? bgn + NUM_POINTS : bgn;   // torch negative wrap
        int ew = end < 0 ? end + NUM_POINTS : end;
        float vb = __ldg(&velocity[bw]) * (1.0f / 3.0f);
        float ve = __ldg(&velocity[ew]) * (1.0f / 3.0f);
        float ab = __ldg(&angles[bw]);
        float ae = __ldg(&angles[ew]);
        float velo3 = fmaf(pos, ve - vb, vb);
        float ang   = fmaf(pos, ae - ab, ab);
        float sn, cs;
        __sincosf(ang, &sn, &cs);
        x = fmaf(x, fmaf(velo3, sn, 1.0f), velo3 * cs);
    }
    return x;
}

// ---------------------------------------------------------------------------
// Kernel 1: build (value, delta) pair table.
// ---------------------------------------------------------------------------
__global__ __launch_bounds__(256)
void build_table_kernel(const float* __restrict__ angles,
                        const float* __restrict__ velocity,
                        const float* __restrict__ coeff,
                        const float* __restrict__ bias)
{
    const float c2l = __ldg(coeff) * 2.8853900817779268f;   // 2*log2(e)*c
    const float b2l = __ldg(bias)  * 2.8853900817779268f;
    const int i = blockIdx.x * 256 + threadIdx.x;
    if (i < TAB_INTERVALS) {
        float x0 = fmaf((float)i,       TAB_H, -4.0f);
        float x1 = fmaf((float)(i + 1), TAB_H, -4.0f);
        float v0 = f3_exact(x0, c2l, b2l, angles, velocity);
        float v1 = f3_exact(x1, c2l, b2l, angles, velocity);
        g_tab[i] = make_float2(v0, v1 - v0);
    }
}

// ---------------------------------------------------------------------------
// Kernel 2: persistent map, output-driven. 64KB table, 2 CTAs/SM, 4-way ILP.
// ---------------------------------------------------------------------------
#define MAP_THREADS 1024
#define MAP_BLOCKS  304                   // 2 CTAs resident per SM x 152 SMs
#define TOTAL_O     (32768 * 256)         // 8,388,608 output float4s
#define ILP 4

extern __shared__ float2 s_tab[];

__device__ __forceinline__ float tab_lookup(float x, float c2l, float b2l,
                                            const float* __restrict__ angles,
                                            const float* __restrict__ velocity)
{
    if (fabsf(x) < 4.0f) {
        float t = fmaf(x, TAB_SCALE, 4.0f * TAB_SCALE);   // (x+4)/h
        int   i = (int)t;                                  // 0..8191
        float fr = t - (float)i;
        float2 vd = s_tab[i];                              // one LDS.64
        return fmaf(fr, vd.y, vd.x);
    }
    return f3_exact(x, c2l, b2l, angles, velocity);        // ~6e-5 of samples
}

__global__ __launch_bounds__(MAP_THREADS)
void macunit_map_kernel(const float2* __restrict__ data,   // [B*256] float2
                        const float4* __restrict__ att,    // [256] float4
                        const float* __restrict__ angles,
                        const float* __restrict__ velocity,
                        const float* __restrict__ coeff,
                        const float* __restrict__ bias,
                        float4* __restrict__ out)          // [B*256] float4
{
    // Stage pair table into shared memory.
    {
        const float2* gt = g_tab;
        for (int i = threadIdx.x; i < TAB_INTERVALS; i += MAP_THREADS)
            s_tab[i] = __ldg(&gt[i]);
    }
    __syncthreads();

    const float c2l = __ldg(coeff) * 2.8853900817779268f;
    const float b2l = __ldg(bias)  * 2.8853900817779268f;

    const int t0 = blockIdx.x * MAP_THREADS + threadIdx.x;
    const int stride = MAP_BLOCKS * MAP_THREADS;            // 311296 (mult of 256)

    // Loop-invariant attention weights (o & 255 == t0 & 255 for all o).
    const float4 a = __ldg(&att[t0 & 255]);

    int o = t0;
    // Main body: ILP front-batched loads.
    while (o + (ILP - 1) * stride < TOTAL_O) {
        float2 d[ILP];
        #pragma unroll
        for (int k = 0; k < ILP; k++)
            d[k] = __ldg(&data[o + k * stride]);

        #pragma unroll
        for (int k = 0; k < ILP; k++) {
            float y0 = tab_lookup(d[k].x, c2l, b2l, angles, velocity);
            float y1 = tab_lookup(d[k].y, c2l, b2l, angles, velocity);
            float4 ov;
            ov.x = a.x * y0;  ov.y = a.y * y0;
            ov.z = a.z * y1;  ov.w = a.w * y1;
            out[o + k * stride] = ov;
        }
        o += ILP * stride;
    }
    // Tail.
    for (; o < TOTAL_O; o += stride) {
        float2 dv = __ldg(&data[o]);
        float y0 = tab_lookup(dv.x, c2l, b2l, angles, velocity);
        float y1 = tab_lookup(dv.y, c2l, b2l, angles, velocity);
        float4 ov;
        ov.x = a.x * y0;  ov.y = a.y * y0;
        ov.z = a.z * y1;  ov.w = a.w * y1;
        out[o] = ov;
    }
}

extern "C" void kernel_launch(void* const* d_in, const int* in_sizes, int n_in,
                              void* d_out, int out_size)
{
    const float2* data     = (const float2*)d_in[0];  // [32768, 512] f32
    const float*  angles   = (const float*) d_in[1];  // [17]
    const float*  velocity = (const float*) d_in[2];  // [17]
    const float4* att      = (const float4*)d_in[3];  // [1024] f32
    const float*  coeff    = (const float*) d_in[4];  // [1]
    const float*  bias     = (const float*) d_in[5];  // [1]
    float4* out = (float4*)d_out;

    static bool attr_set = false;
    if (!attr_set) {
        cudaFuncSetAttribute(macunit_map_kernel,
                             cudaFuncAttributeMaxDynamicSharedMemorySize,
                             TAB_BYTES);
        attr_set = true;
    }

    build_table_kernel<<<(TAB_INTERVALS + 255) / 256, 256>>>(angles, velocity, coeff, bias);

    macunit_map_kernel<<<MAP_BLOCKS, MAP_THREADS, TAB_BYTES>>>(
        data, att, angles, velocity, coeff, bias, out);
}